// round 5
// baseline (speedup 1.0000x reference)
#include <cuda_runtime.h>
#include <cuda_bf16.h>

// ---------------- problem constants ----------------
#define QN    2500      // HB*WB
#define NKK   10080     // N*H_IMG*W_IMG
#define DD    128
#define HEADS 4
#define DH    32
#define HWIMG 1680      // 28*60
#define SCALE 0.17677669529663687f   // 32^-0.5

// ---------------- scratch (__device__ globals: no allocation allowed) ------
__device__ float g_qh [QN  * DD];
__device__ float g_kh [NKK * DD];
__device__ float g_vh [NKK * DD];
__device__ float g_att[QN  * DD];

// =====================================================================
// Kernel 1: LayerNorm + 128x128 projection.
//   mode 0: src is q-layout  [D, 2500]           -> x[row][d] = src[d*2500 + row]
//   mode 1: src is k-layout  [N, D, 28, 60]      -> x[row][d] = src[(n*128+d)*1680 + hw]
// One block = 32 rows, 256 threads.
// =====================================================================
__global__ __launch_bounds__(256)
void ln_proj_kernel(const float* __restrict__ src,
                    const float* __restrict__ lnw, const float* __restrict__ lnb,
                    const float* __restrict__ Wm,  const float* __restrict__ bias,
                    float* __restrict__ out, int nrows, int mode)
{
    __shared__ float xs[32][129];
    const int tid  = threadIdx.x;
    const int row0 = blockIdx.x * 32;

    // ---- load tile (coalesced over rows) ----
    #pragma unroll
    for (int i = 0; i < 16; i++) {
        int idx = tid + 256 * i;
        int r = idx & 31, d = idx >> 5;
        int row = row0 + r;
        float v = 0.f;
        if (row < nrows) {
            int addr;
            if (mode == 0) {
                addr = d * QN + row;
            } else {
                int n  = row / HWIMG;
                int hw = row - n * HWIMG;
                addr = (n * DD + d) * HWIMG + hw;
            }
            v = src[addr];
        }
        xs[r][d] = v;
    }
    __syncthreads();

    // ---- LayerNorm: 8 threads per row ----
    {
        int r = tid >> 3, sub = tid & 7;
        float s = 0.f, s2 = 0.f;
        #pragma unroll
        for (int kk = 0; kk < 16; kk++) {
            float x = xs[r][sub + 8 * kk];
            s += x; s2 += x * x;
        }
        #pragma unroll
        for (int o = 4; o; o >>= 1) {
            s  += __shfl_xor_sync(0xffffffffu, s,  o);
            s2 += __shfl_xor_sync(0xffffffffu, s2, o);
        }
        float mean = s * (1.f / 128.f);
        float var  = s2 * (1.f / 128.f) - mean * mean;
        float rs   = rsqrtf(var + 1e-5f);
        #pragma unroll
        for (int kk = 0; kk < 16; kk++) {
            int d = sub + 8 * kk;
            xs[r][d] = (xs[r][d] - mean) * rs * lnw[d] + lnb[d];
        }
    }
    __syncthreads();

    // ---- GEMM: 32x128 = xs(32x128) @ Wm(128x128) + bias ----
    const int j  = tid & 127;
    const int rb = tid >> 7;          // 0 / 1 -> rows rb*16 .. rb*16+15
    float acc[16];
    float bj = bias[j];
    #pragma unroll
    for (int i = 0; i < 16; i++) acc[i] = bj;

    for (int d = 0; d < 128; d++) {
        float wv = Wm[d * 128 + j];
        #pragma unroll
        for (int i = 0; i < 16; i++)
            acc[i] = fmaf(xs[rb * 16 + i][d], wv, acc[i]);
    }
    #pragma unroll
    for (int i = 0; i < 16; i++) {
        int row = row0 + rb * 16 + i;
        if (row < nrows) out[row * 128 + j] = acc[i];
    }
}

// =====================================================================
// Kernel 2: fused attention.
// Single-pass (no max subtraction needed: logits tiny; masked -> exp(-FLT_MAX*W)=0,
// and W==0 masked -> exp(-0)=1, matching the reference exactly).
// p = exp(A*dot + B),  A = SCALE*W (visible) else 0,  B = 0 (visible) else -FLT_MAX*W.
// Block = 16 q-rows, 256 threads = 64 (q,head) pairs x 4 key-slices.
// =====================================================================
#define BQ 16
#define TK 32

__global__ __launch_bounds__(256, 2)
void attn_kernel(const float* __restrict__ Wl, const int* __restrict__ vis,
                 const float* __restrict__ qh, const float* __restrict__ kh,
                 const float* __restrict__ vh, float* __restrict__ att)
{
    __shared__ float4 ks[TK * 32];      // 32 keys x 128 floats
    __shared__ float4 vs[TK * 32];
    __shared__ float  As[BQ][TK + 1];
    __shared__ float  Bs[BQ][TK + 1];

    const int tid   = threadIdx.x;
    const int pair  = tid & 63;
    const int slice = tid >> 6;         // 0..3
    const int ql    = pair >> 2;        // 0..15
    const int head  = pair & 3;
    const int q0    = blockIdx.x * BQ;
    const bool qok  = (q0 + ql) < QN;

    float4 qv[8];
    if (qok) {
        const float4* qp = (const float4*)(qh + (q0 + ql) * 128 + head * 32);
        #pragma unroll
        for (int c = 0; c < 8; c++) qv[c] = qp[c];
    } else {
        #pragma unroll
        for (int c = 0; c < 8; c++) qv[c] = make_float4(0.f, 0.f, 0.f, 0.f);
    }

    float4 acc[8];
    #pragma unroll
    for (int c = 0; c < 8; c++) acc[c] = make_float4(0.f, 0.f, 0.f, 0.f);
    float ssum = 0.f;

    for (int k0 = 0; k0 < NKK; k0 += TK) {
        __syncthreads();   // previous tile fully consumed
        // ---- stage K/V tile (1024 float4 each, 4 per thread) ----
        const float4* kg = (const float4*)(kh + k0 * 128);
        const float4* vg = (const float4*)(vh + k0 * 128);
        #pragma unroll
        for (int i = 0; i < 4; i++) {
            ks[tid + 256 * i] = kg[tid + 256 * i];
            vs[tid + 256 * i] = vg[tid + 256 * i];
        }
        // ---- stage fused (A,B) from W_logits/vis ----
        #pragma unroll
        for (int i = 0; i < 2; i++) {
            int idx = tid + 256 * i;            // 512 = BQ*TK
            int r = idx >> 5, jj = idx & 31;
            int qrow = q0 + r;
            float Aa = 0.f, Bb = 0.f;
            if (qrow < QN) {
                int off = qrow * NKK + k0 + jj;
                float w = Wl[off];
                if (vis[off]) { Aa = SCALE * w; Bb = 0.f; }
                else          { Aa = 0.f;       Bb = -3.402823466e38f * w; }
            }
            As[r][jj] = Aa;
            Bs[r][jj] = Bb;
        }
        __syncthreads();

        // ---- compute: each thread handles keys j = slice, slice+4, ... ----
        #pragma unroll 2
        for (int j = slice; j < TK; j += 4) {
            const float4* kr = &ks[j * 32 + head * 8];
            float d0 = 0.f, d1 = 0.f, d2 = 0.f, d3 = 0.f;
            #pragma unroll
            for (int c = 0; c < 8; c++) {
                float4 kk = kr[c];
                d0 = fmaf(qv[c].x, kk.x, d0);
                d1 = fmaf(qv[c].y, kk.y, d1);
                d2 = fmaf(qv[c].z, kk.z, d2);
                d3 = fmaf(qv[c].w, kk.w, d3);
            }
            float dot = (d0 + d1) + (d2 + d3);
            float p = __expf(fmaf(As[ql][j], dot, Bs[ql][j]));
            ssum += p;
            const float4* vr = &vs[j * 32 + head * 8];
            #pragma unroll
            for (int c = 0; c < 8; c++) {
                float4 vv = vr[c];
                acc[c].x = fmaf(p, vv.x, acc[c].x);
                acc[c].y = fmaf(p, vv.y, acc[c].y);
                acc[c].z = fmaf(p, vv.z, acc[c].z);
                acc[c].w = fmaf(p, vv.w, acc[c].w);
            }
        }
    }

    // ---- combine the 4 key-slices (reuse ks as scratch: 64 pairs x 36 floats) ----
    float* red = (float*)ks;
    for (int sl = 1; sl < 4; sl++) {
        __syncthreads();
        if (slice == sl) {
            float* rp = red + pair * 36;
            #pragma unroll
            for (int c = 0; c < 8; c++) {
                rp[c * 4 + 0] = acc[c].x; rp[c * 4 + 1] = acc[c].y;
                rp[c * 4 + 2] = acc[c].z; rp[c * 4 + 3] = acc[c].w;
            }
            rp[32] = ssum;
        }
        __syncthreads();
        if (slice == 0) {
            const float* rp = red + pair * 36;
            #pragma unroll
            for (int c = 0; c < 8; c++) {
                acc[c].x += rp[c * 4 + 0]; acc[c].y += rp[c * 4 + 1];
                acc[c].z += rp[c * 4 + 2]; acc[c].w += rp[c * 4 + 3];
            }
            ssum += rp[32];
        }
    }
    if (slice == 0 && qok) {
        float inv = 1.f / ssum;
        float4* op = (float4*)(att + (q0 + ql) * 128 + head * 32);
        #pragma unroll
        for (int c = 0; c < 8; c++) {
            float4 o;
            o.x = acc[c].x * inv; o.y = acc[c].y * inv;
            o.z = acc[c].z * inv; o.w = acc[c].w * inv;
            op[c] = o;
        }
    }
}

// =====================================================================
// Kernel 3: epilogue per q-row: proj + skip + LN + MLP(GELU exact) + LN,
// write transposed [D, Q] output.
// =====================================================================
__device__ __forceinline__ void block_reduce2(float& s, float& s2, float* buf)
{
    #pragma unroll
    for (int o = 16; o; o >>= 1) {
        s  += __shfl_xor_sync(0xffffffffu, s,  o);
        s2 += __shfl_xor_sync(0xffffffffu, s2, o);
    }
    int w = threadIdx.x >> 5, l = threadIdx.x & 31;
    if (l == 0) { buf[w] = s; buf[4 + w] = s2; }
    __syncthreads();
    s  = buf[0] + buf[1] + buf[2] + buf[3];
    s2 = buf[4] + buf[5] + buf[6] + buf[7];
    __syncthreads();
}

__global__ __launch_bounds__(128)
void epilogue_kernel(const float* __restrict__ att,
                     const float* __restrict__ wp,   const float* __restrict__ bp,
                     const float* __restrict__ skip,
                     const float* __restrict__ prew, const float* __restrict__ preb,
                     const float* __restrict__ w1,   const float* __restrict__ b1,
                     const float* __restrict__ w2,   const float* __restrict__ b2,
                     const float* __restrict__ postw,const float* __restrict__ postb,
                     float* __restrict__ out)
{
    __shared__ float a[128];
    __shared__ float zsm[128];
    __shared__ float h[256];
    __shared__ float rbuf[8];

    const int row = blockIdx.x;
    const int j   = threadIdx.x;

    a[j] = att[row * 128 + j];
    __syncthreads();

    // out-projection + skip
    float t = bp[j];
    #pragma unroll 4
    for (int d = 0; d < 128; d++) t = fmaf(a[d], wp[d * 128 + j], t);
    t += skip[j * QN + row];

    // pre-LN
    float s = t, s2 = t * t;
    block_reduce2(s, s2, rbuf);
    float mean = s * (1.f / 128.f);
    float var  = s2 * (1.f / 128.f) - mean * mean;
    float zj = (t - mean) * rsqrtf(var + 1e-5f) * prew[j] + preb[j];
    zsm[j] = zj;
    __syncthreads();

    // MLP hidden (2 cols per thread), exact GELU
    #pragma unroll
    for (int cc = 0; cc < 2; cc++) {
        int c = j + cc * 128;
        float hv = b1[c];
        #pragma unroll 4
        for (int d = 0; d < 128; d++) hv = fmaf(zsm[d], w1[d * 256 + c], hv);
        h[c] = 0.5f * hv * (1.0f + erff(hv * 0.70710678118654752f));
    }
    __syncthreads();

    float y = b2[j];
    #pragma unroll 4
    for (int c = 0; c < 256; c++) y = fmaf(h[c], w2[c * 128 + j], y);
    y += zj;

    // post-LN
    float ps = y, ps2 = y * y;
    block_reduce2(ps, ps2, rbuf);
    float m2 = ps * (1.f / 128.f);
    float v2 = ps2 * (1.f / 128.f) - m2 * m2;
    float o = (y - m2) * rsqrtf(v2 + 1e-5f) * postw[j] + postb[j];

    out[j * QN + row] = o;
}

// =====================================================================
extern "C" void kernel_launch(void* const* d_in, const int* in_sizes, int n_in,
                              void* d_out, int out_size)
{
    const float* q      = (const float*)d_in[0];
    const float* k      = (const float*)d_in[1];
    const float* v      = (const float*)d_in[2];
    const float* Wl     = (const float*)d_in[3];
    const int*   vis    = (const int*)  d_in[4];
    const float* skip   = (const float*)d_in[5];
    const float* qn_w   = (const float*)d_in[6];
    const float* qn_b   = (const float*)d_in[7];
    const float* kn_w   = (const float*)d_in[8];
    const float* kn_b   = (const float*)d_in[9];
    const float* vn_w   = (const float*)d_in[10];
    const float* vn_b   = (const float*)d_in[11];
    const float* pre_w  = (const float*)d_in[12];
    const float* pre_b  = (const float*)d_in[13];
    const float* post_w = (const float*)d_in[14];
    const float* post_b = (const float*)d_in[15];
    const float* wq     = (const float*)d_in[16];
    const float* bq     = (const float*)d_in[17];
    const float* wk     = (const float*)d_in[18];
    const float* bk     = (const float*)d_in[19];
    const float* wv     = (const float*)d_in[20];
    const float* bv     = (const float*)d_in[21];
    const float* wp     = (const float*)d_in[22];
    const float* bp     = (const float*)d_in[23];
    const float* w1     = (const float*)d_in[24];
    const float* b1     = (const float*)d_in[25];
    const float* w2     = (const float*)d_in[26];
    const float* b2     = (const float*)d_in[27];
    float* out = (float*)d_out;

    float *qh, *kh, *vh, *att;
    cudaGetSymbolAddress((void**)&qh,  g_qh);
    cudaGetSymbolAddress((void**)&kh,  g_kh);
    cudaGetSymbolAddress((void**)&vh,  g_vh);
    cudaGetSymbolAddress((void**)&att, g_att);

    ln_proj_kernel<<<(QN + 31) / 32, 256>>>(q, qn_w, qn_b, wq, bq, qh, QN, 0);
    ln_proj_kernel<<<NKK / 32, 256>>>(k, kn_w, kn_b, wk, bk, kh, NKK, 1);
    ln_proj_kernel<<<NKK / 32, 256>>>(v, vn_w, vn_b, wv, bv, vh, NKK, 1);

    attn_kernel<<<(QN + BQ - 1) / BQ, 256>>>(Wl, vis, qh, kh, vh, att);

    epilogue_kernel<<<QN, 128>>>(att, wp, bp, skip, pre_w, pre_b,
                                 w1, b1, w2, b2, post_w, post_b, out);
}

// round 6
// speedup vs baseline: 5.1124x; 5.1124x over previous
#include <cuda_runtime.h>

// ---------------- problem constants ----------------
#define QN    2500
#define NKK   10080
#define NKP   10112      // padded to 158*64 (pad rows stay zero: __device__ zero-init, never written)
#define HWIMG 1680
#define SCALE 0.17677669529663687f   // 32^-0.5
#define NEGBIG 3.402823466e38f

#define BQ     32
#define TKK    64
#define NT_TOT 158       // ceil(10080/64) with padding
#define SPLITS 12
#define QT     79        // ceil(2500/32)
#define QPAD   (QT*BQ)   // 2528

// ---------------- scratch ----------------
__device__ float g_qh [QPAD * 128];
__device__ float g_kh [NKP  * 128];
__device__ float g_vh [NKP  * 128];
__device__ float g_po [SPLITS * QPAD * 128];
__device__ float g_ps [SPLITS * QPAD * 4];

// =====================================================================
// Kernel 1: LayerNorm + 128x128 projection (unchanged from R5; passes).
// =====================================================================
__global__ __launch_bounds__(256)
void ln_proj_kernel(const float* __restrict__ src,
                    const float* __restrict__ lnw, const float* __restrict__ lnb,
                    const float* __restrict__ Wm,  const float* __restrict__ bias,
                    float* __restrict__ out, int nrows, int mode)
{
    __shared__ float xs[32][129];
    const int tid  = threadIdx.x;
    const int row0 = blockIdx.x * 32;

    #pragma unroll
    for (int i = 0; i < 16; i++) {
        int idx = tid + 256 * i;
        int r = idx & 31, d = idx >> 5;
        int row = row0 + r;
        float v = 0.f;
        if (row < nrows) {
            int addr;
            if (mode == 0) addr = d * QN + row;
            else {
                int n  = row / HWIMG;
                int hw = row - n * HWIMG;
                addr = (n * 128 + d) * HWIMG + hw;
            }
            v = src[addr];
        }
        xs[r][d] = v;
    }
    __syncthreads();
    {
        int r = tid >> 3, sub = tid & 7;
        float s = 0.f, s2 = 0.f;
        #pragma unroll
        for (int kk = 0; kk < 16; kk++) {
            float x = xs[r][sub + 8 * kk];
            s += x; s2 += x * x;
        }
        #pragma unroll
        for (int o = 4; o; o >>= 1) {
            s  += __shfl_xor_sync(0xffffffffu, s,  o);
            s2 += __shfl_xor_sync(0xffffffffu, s2, o);
        }
        float mean = s * (1.f / 128.f);
        float var  = s2 * (1.f / 128.f) - mean * mean;
        float rs   = rsqrtf(var + 1e-5f);
        #pragma unroll
        for (int kk = 0; kk < 16; kk++) {
            int d = sub + 8 * kk;
            xs[r][d] = (xs[r][d] - mean) * rs * lnw[d] + lnb[d];
        }
    }
    __syncthreads();

    const int j  = tid & 127;
    const int rb = tid >> 7;
    float acc[16];
    float bj = bias[j];
    #pragma unroll
    for (int i = 0; i < 16; i++) acc[i] = bj;
    for (int d = 0; d < 128; d++) {
        float wv = Wm[d * 128 + j];
        #pragma unroll
        for (int i = 0; i < 16; i++)
            acc[i] = fmaf(xs[rb * 16 + i][d], wv, acc[i]);
    }
    #pragma unroll
    for (int i = 0; i < 16; i++) {
        int row = row0 + rb * 16 + i;
        if (row < nrows) out[row * 128 + j] = acc[i];
    }
}

// =====================================================================
// Kernel 2: register-blocked tiled attention, key-split.
// Grid = SPLITS*QT blocks of 256 threads, 2 blocks/SM.
// Per tile: stage K + A/B -> GEMM S (regs) -> exp -> P smem -> stage V -> GEMM O.
// =====================================================================
#define SMEM_FLOATS (32*128 + 64*128 + 2*32*68 + 4*32*68)   // 25344 floats = 101376 B

__global__ __launch_bounds__(256, 2)
void attn2_kernel(const float* __restrict__ Wl, const int* __restrict__ vis)
{
    extern __shared__ float sm[];
    float* Qs = sm;                      // [32][128] float4-swizzled by (r>>2)
    float* KV = Qs + 32 * 128;           // [64][128] float4-swizzled by (j&7)
    float* As = KV + 64 * 128;           // [32][68]
    float* Bs = As + 32 * 68;            // [32][68]
    float* Ps = Bs + 32 * 68;            // [4][32][68]

    const int tid  = threadIdx.x;
    const int w    = tid >> 5, lane = tid & 31;
    const int sp   = blockIdx.x / QT;
    const int qt   = blockIdx.x % QT;
    const int q0   = qt * BQ;
    const int t0   = (NT_TOT * sp) / SPLITS;
    const int t1   = (NT_TOT * (sp + 1)) / SPLITS;

    // phase A roles: warp = (head, half); lane = (qgA, kgA)
    const int hA  = w >> 1, half = w & 1;
    const int qgA = lane >> 3, kgA = lane & 7;
    const int qbA = half * 16 + qgA * 4;     // 4 q-rows qbA..qbA+3
    // phase B roles: warp covers d in [w*16, w*16+16), head hB = w>>1
    const int qgB = lane >> 2, dgB = lane & 3;
    const int d4B = w * 4 + dgB;             // float4-chunk index of this lane's d

    // ---- stage Q tile once ----
    #pragma unroll
    for (int i = 0; i < 4; i++) {
        int idx4 = tid + 256 * i;            // 1024 float4
        int r = idx4 >> 5, d4 = idx4 & 31;
        int row = q0 + r;
        float4 v = make_float4(0.f, 0.f, 0.f, 0.f);
        if (row < QN) v = ((const float4*)g_qh)[row * 32 + d4];
        ((float4*)Qs)[r * 32 + (d4 ^ (r >> 2))] = v;
    }

    float4 accO[4];
    #pragma unroll
    for (int iq = 0; iq < 4; iq++) accO[iq] = make_float4(0.f, 0.f, 0.f, 0.f);
    float ssum[4] = {0.f, 0.f, 0.f, 0.f};

    for (int t = t0; t < t1; t++) {
        const int jb = t * TKK;
        __syncthreads();                     // buffers free (prev phase B done)

        // ---- stage K (swizzled) ----
        #pragma unroll
        for (int i = 0; i < 8; i++) {
            int idx4 = tid + 256 * i;        // 2048 float4
            int j = idx4 >> 5, d4 = idx4 & 31;
            float4 v = ((const float4*)g_kh)[(jb + j) * 32 + d4];
            ((float4*)KV)[j * 32 + (d4 ^ (j & 7))] = v;
        }
        // ---- stage A/B (mask+weight folded; single read of W/vis per block) ----
        #pragma unroll
        for (int i = 0; i < 2; i++) {
            int idx4 = tid + 256 * i;        // 512 float4 = 32q x 16 chunks
            int q = idx4 >> 4, c4 = idx4 & 15;
            int qrow = q0 + q;
            int jg = jb + c4 * 4;
            float Aa[4], Bb[4];
            if (qrow < QN && jg + 3 < NKK) {
                const float4 wv = *(const float4*)(Wl + (size_t)qrow * NKK + jg);
                const int4   vv = *(const int4*) (vis + (size_t)qrow * NKK + jg);
                Aa[0] = vv.x ? SCALE * wv.x : 0.f;  Bb[0] = vv.x ? 0.f : -NEGBIG * wv.x;
                Aa[1] = vv.y ? SCALE * wv.y : 0.f;  Bb[1] = vv.y ? 0.f : -NEGBIG * wv.y;
                Aa[2] = vv.z ? SCALE * wv.z : 0.f;  Bb[2] = vv.z ? 0.f : -NEGBIG * wv.z;
                Aa[3] = vv.w ? SCALE * wv.w : 0.f;  Bb[3] = vv.w ? 0.f : -NEGBIG * wv.w;
            } else {
                #pragma unroll
                for (int e = 0; e < 4; e++) {
                    int jge = jg + e;
                    float av = 0.f, bv = -NEGBIG;
                    if (qrow < QN && jge < NKK) {
                        float wv = Wl[(size_t)qrow * NKK + jge];
                        int   vb = vis[(size_t)qrow * NKK + jge];
                        if (vb) { av = SCALE * wv; bv = 0.f; }
                        else    { av = 0.f;        bv = -NEGBIG * wv; }
                    }
                    Aa[e] = av; Bb[e] = bv;
                }
            }
            *(float4*)(As + q * 68 + c4 * 4) = make_float4(Aa[0], Aa[1], Aa[2], Aa[3]);
            *(float4*)(Bs + q * 68 + c4 * 4) = make_float4(Bb[0], Bb[1], Bb[2], Bb[3]);
        }
        __syncthreads();

        // ---- phase A: S[iq][ik] = q . k (head hA, 32 dims) ----
        float accS[4][8];
        #pragma unroll
        for (int iq = 0; iq < 4; iq++)
            #pragma unroll
            for (int ik = 0; ik < 8; ik++) accS[iq][ik] = 0.f;

        #pragma unroll
        for (int c4 = 0; c4 < 8; c4++) {
            const int d4  = hA * 8 + c4;
            const int qsw = d4 ^ (half * 4 + qgA);
            const int ksw = d4 ^ kgA;
            float4 qv[4];
            #pragma unroll
            for (int iq = 0; iq < 4; iq++)
                qv[iq] = ((const float4*)Qs)[(qbA + iq) * 32 + qsw];
            #pragma unroll
            for (int ik = 0; ik < 8; ik++) {
                const int j = kgA + 8 * ik;
                float4 kv = ((const float4*)KV)[j * 32 + ksw];
                #pragma unroll
                for (int iq = 0; iq < 4; iq++) {
                    accS[iq][ik] = fmaf(qv[iq].x, kv.x, accS[iq][ik]);
                    accS[iq][ik] = fmaf(qv[iq].y, kv.y, accS[iq][ik]);
                    accS[iq][ik] = fmaf(qv[iq].z, kv.z, accS[iq][ik]);
                    accS[iq][ik] = fmaf(qv[iq].w, kv.w, accS[iq][ik]);
                }
            }
        }

        // ---- exp + P store + ssum (own regs; no cross-warp dep) ----
        #pragma unroll
        for (int iq = 0; iq < 4; iq++) {
            const int q = qbA + iq;
            const float* ar = As + q * 68;
            const float* br = Bs + q * 68;
            float* pr = Ps + (hA * 32 + q) * 68;
            #pragma unroll
            for (int ik = 0; ik < 8; ik++) {
                const int j = kgA + 8 * ik;
                float p = __expf(fmaf(ar[j], accS[iq][ik], br[j]));
                ssum[iq] += p;
                pr[j] = p;
            }
        }
        __syncthreads();                     // K consumed by all, P complete

        // ---- stage V into the same buffer ----
        #pragma unroll
        for (int i = 0; i < 8; i++) {
            int idx4 = tid + 256 * i;
            int j = idx4 >> 5, d4 = idx4 & 31;
            float4 v = ((const float4*)g_vh)[(jb + j) * 32 + d4];
            ((float4*)KV)[j * 32 + (d4 ^ (j & 7))] = v;
        }
        __syncthreads();

        // ---- phase B: O[32q][16d per warp] += P @ V ----
        const int hB = w >> 1;
        #pragma unroll 2
        for (int j4 = 0; j4 < 16; j4++) {
            float4 pv[4];
            #pragma unroll
            for (int iq = 0; iq < 4; iq++)
                pv[iq] = ((const float4*)Ps)[(hB * 32 + qgB + 8 * iq) * 17 + j4];
            float4 vv[4];
            #pragma unroll
            for (int ij = 0; ij < 4; ij++) {
                const int j = j4 * 4 + ij;
                vv[ij] = ((const float4*)KV)[j * 32 + (d4B ^ (j & 7))];
            }
            #pragma unroll
            for (int iq = 0; iq < 4; iq++) {
                accO[iq].x = fmaf(pv[iq].x, vv[0].x, accO[iq].x);
                accO[iq].y = fmaf(pv[iq].x, vv[0].y, accO[iq].y);
                accO[iq].z = fmaf(pv[iq].x, vv[0].z, accO[iq].z);
                accO[iq].w = fmaf(pv[iq].x, vv[0].w, accO[iq].w);
                accO[iq].x = fmaf(pv[iq].y, vv[1].x, accO[iq].x);
                accO[iq].y = fmaf(pv[iq].y, vv[1].y, accO[iq].y);
                accO[iq].z = fmaf(pv[iq].y, vv[1].z, accO[iq].z);
                accO[iq].w = fmaf(pv[iq].y, vv[1].w, accO[iq].w);
                accO[iq].x = fmaf(pv[iq].z, vv[2].x, accO[iq].x);
                accO[iq].y = fmaf(pv[iq].z, vv[2].y, accO[iq].y);
                accO[iq].z = fmaf(pv[iq].z, vv[2].z, accO[iq].z);
                accO[iq].w = fmaf(pv[iq].z, vv[2].w, accO[iq].w);
                accO[iq].x = fmaf(pv[iq].w, vv[3].x, accO[iq].x);
                accO[iq].y = fmaf(pv[iq].w, vv[3].y, accO[iq].y);
                accO[iq].z = fmaf(pv[iq].w, vv[3].z, accO[iq].z);
                accO[iq].w = fmaf(pv[iq].w, vv[3].w, accO[iq].w);
            }
        }
    }

    // ---- write partials ----
    // ssum reduce across kgA (low 3 lane bits)
    #pragma unroll
    for (int o = 1; o < 8; o <<= 1)
        #pragma unroll
        for (int iq = 0; iq < 4; iq++)
            ssum[iq] += __shfl_xor_sync(0xffffffffu, ssum[iq], o);
    if (kgA == 0) {
        #pragma unroll
        for (int iq = 0; iq < 4; iq++)
            g_ps[((size_t)sp * QPAD + q0 + qbA + iq) * 4 + hA] = ssum[iq];
    }
    #pragma unroll
    for (int iq = 0; iq < 4; iq++) {
        const int q = qgB + 8 * iq;
        ((float4*)g_po)[((size_t)sp * QPAD + q0 + q) * 32 + w * 4 + dgB] = accO[iq];
    }
}

// =====================================================================
// Kernel 3: combine partials + proj + skip + LN + MLP(GELU) + LN.
// =====================================================================
__device__ __forceinline__ void block_reduce2(float& s, float& s2, float* buf)
{
    #pragma unroll
    for (int o = 16; o; o >>= 1) {
        s  += __shfl_xor_sync(0xffffffffu, s,  o);
        s2 += __shfl_xor_sync(0xffffffffu, s2, o);
    }
    int w = threadIdx.x >> 5, l = threadIdx.x & 31;
    if (l == 0) { buf[w] = s; buf[4 + w] = s2; }
    __syncthreads();
    s  = buf[0] + buf[1] + buf[2] + buf[3];
    s2 = buf[4] + buf[5] + buf[6] + buf[7];
    __syncthreads();
}

__global__ __launch_bounds__(128)
void epilogue_kernel(const float* __restrict__ wp,   const float* __restrict__ bp,
                     const float* __restrict__ skip,
                     const float* __restrict__ prew, const float* __restrict__ preb,
                     const float* __restrict__ w1,   const float* __restrict__ b1,
                     const float* __restrict__ w2,   const float* __restrict__ b2,
                     const float* __restrict__ postw,const float* __restrict__ postb,
                     float* __restrict__ out)
{
    __shared__ float a[128];
    __shared__ float zsm[128];
    __shared__ float h[256];
    __shared__ float rbuf[8];

    const int row = blockIdx.x;
    const int j   = threadIdx.x;
    const int hd  = j >> 5;

    // combine key-split partials
    float denom = 0.f, av = 0.f;
    #pragma unroll
    for (int s = 0; s < SPLITS; s++) {
        size_t base = (size_t)s * QPAD + row;
        denom += g_ps[base * 4 + hd];
        av    += g_po[base * 128 + j];
    }
    a[j] = av / denom;
    __syncthreads();

    float t = bp[j];
    #pragma unroll 4
    for (int d = 0; d < 128; d++) t = fmaf(a[d], wp[d * 128 + j], t);
    t += skip[j * QN + row];

    float s = t, s2 = t * t;
    block_reduce2(s, s2, rbuf);
    float mean = s * (1.f / 128.f);
    float var  = s2 * (1.f / 128.f) - mean * mean;
    float zj = (t - mean) * rsqrtf(var + 1e-5f) * prew[j] + preb[j];
    zsm[j] = zj;
    __syncthreads();

    #pragma unroll
    for (int cc = 0; cc < 2; cc++) {
        int c = j + cc * 128;
        float hv = b1[c];
        #pragma unroll 4
        for (int d = 0; d < 128; d++) hv = fmaf(zsm[d], w1[d * 256 + c], hv);
        h[c] = 0.5f * hv * (1.0f + erff(hv * 0.70710678118654752f));
    }
    __syncthreads();

    float y = b2[j];
    #pragma unroll 4
    for (int c = 0; c < 256; c++) y = fmaf(h[c], w2[c * 128 + j], y);
    y += zj;

    float ps = y, ps2 = y * y;
    block_reduce2(ps, ps2, rbuf);
    float m2 = ps * (1.f / 128.f);
    float v2 = ps2 * (1.f / 128.f) - m2 * m2;
    out[j * QN + row] = (y - m2) * rsqrtf(v2 + 1e-5f) * postw[j] + postb[j];
}

// =====================================================================
extern "C" void kernel_launch(void* const* d_in, const int* in_sizes, int n_in,
                              void* d_out, int out_size)
{
    const float* q      = (const float*)d_in[0];
    const float* k      = (const float*)d_in[1];
    const float* v      = (const float*)d_in[2];
    const float* Wl     = (const float*)d_in[3];
    const int*   vis    = (const int*)  d_in[4];
    const float* skip   = (const float*)d_in[5];
    const float* qn_w   = (const float*)d_in[6];
    const float* qn_b   = (const float*)d_in[7];
    const float* kn_w   = (const float*)d_in[8];
    const float* kn_b   = (const float*)d_in[9];
    const float* vn_w   = (const float*)d_in[10];
    const float* vn_b   = (const float*)d_in[11];
    const float* pre_w  = (const float*)d_in[12];
    const float* pre_b  = (const float*)d_in[13];
    const float* post_w = (const float*)d_in[14];
    const float* post_b = (const float*)d_in[15];
    const float* wq     = (const float*)d_in[16];
    const float* bq     = (const float*)d_in[17];
    const float* wk     = (const float*)d_in[18];
    const float* bk     = (const float*)d_in[19];
    const float* wv     = (const float*)d_in[20];
    const float* bv     = (const float*)d_in[21];
    const float* wp     = (const float*)d_in[22];
    const float* bp     = (const float*)d_in[23];
    const float* w1     = (const float*)d_in[24];
    const float* b1     = (const float*)d_in[25];
    const float* w2     = (const float*)d_in[26];
    const float* b2     = (const float*)d_in[27];
    float* out = (float*)d_out;

    float *qh, *kh, *vh;
    cudaGetSymbolAddress((void**)&qh, g_qh);
    cudaGetSymbolAddress((void**)&kh, g_kh);
    cudaGetSymbolAddress((void**)&vh, g_vh);

    cudaFuncSetAttribute(attn2_kernel,
                         cudaFuncAttributeMaxDynamicSharedMemorySize,
                         SMEM_FLOATS * 4);

    ln_proj_kernel<<<(QN + 31) / 32, 256>>>(q, qn_w, qn_b, wq, bq, qh, QN, 0);
    ln_proj_kernel<<<NKK / 32, 256>>>(k, kn_w, kn_b, wk, bk, kh, NKK, 1);
    ln_proj_kernel<<<NKK / 32, 256>>>(v, vn_w, vn_b, wv, bv, vh, NKK, 1);

    attn2_kernel<<<SPLITS * QT, 256, SMEM_FLOATS * 4>>>(Wl, vis);

    epilogue_kernel<<<QN, 128>>>(wp, bp, skip, pre_w, pre_b,
                                 w1, b1, w2, b2, post_w, post_b, out);
}

// round 12
// speedup vs baseline: 11.3918x; 2.2283x over previous
#include <cuda_runtime.h>

// ---------------- problem constants ----------------
#define QN    2500
#define NKK   10080
#define NKP   10112
#define HWIMG 1680
#define SCALE 0.17677669529663687f   // 32^-0.5
#define NEGBIG 3.402823466e38f

#define BQ     32
#define TKK    64
#define NT_TOT 158       // ceil(10080/64), padded keys are zero + masked
#define SPLITS 12
#define QT     79
#define QPAD   (QT*BQ)   // 2528

#define KSTRIDE 132      // K smem row stride (floats): conflict-free K-frag loads
#define VSTRIDE 136      // V smem row stride: conflict-free V-frag loads
#define PSTRIDE 68       // P / A / B smem row stride

// ---------------- scratch ----------------
__device__ float g_qh [QPAD * 128];
__device__ float g_kh [NKP  * 128];
__device__ float g_vh [NKP  * 128];
__device__ float g_po [SPLITS * QPAD * 128];
__device__ float g_ps [SPLITS * QPAD * 4];

// ---------------- mma helpers ----------------
__device__ __forceinline__ void mma_tf32(float c[4], const unsigned a[4],
                                         unsigned b0, unsigned b1)
{
    asm volatile(
        "mma.sync.aligned.m16n8k8.row.col.f32.tf32.tf32.f32 "
        "{%0,%1,%2,%3}, {%4,%5,%6,%7}, {%8,%9}, {%0,%1,%2,%3};\n"
        : "+f"(c[0]), "+f"(c[1]), "+f"(c[2]), "+f"(c[3])
        : "r"(a[0]), "r"(a[1]), "r"(a[2]), "r"(a[3]), "r"(b0), "r"(b1));
}
__device__ __forceinline__ float f_tf32(float f)
{
    unsigned r;
    asm("cvt.rna.tf32.f32 %0, %1;" : "=r"(r) : "f"(f));
    return __uint_as_float(r);
}

// =====================================================================
// Kernel 1: LayerNorm + 128x128 projection; outputs tf32-rounded fp32.
// =====================================================================
__global__ __launch_bounds__(256)
void ln_proj_kernel(const float* __restrict__ src,
                    const float* __restrict__ lnw, const float* __restrict__ lnb,
                    const float* __restrict__ Wm,  const float* __restrict__ bias,
                    float* __restrict__ out, int nrows, int mode)
{
    __shared__ float xs[32][129];
    const int tid  = threadIdx.x;
    const int row0 = blockIdx.x * 32;

    #pragma unroll
    for (int i = 0; i < 16; i++) {
        int idx = tid + 256 * i;
        int r = idx & 31, d = idx >> 5;
        int row = row0 + r;
        float v = 0.f;
        if (row < nrows) {
            int addr;
            if (mode == 0) addr = d * QN + row;
            else {
                int n  = row / HWIMG;
                int hw = row - n * HWIMG;
                addr = (n * 128 + d) * HWIMG + hw;
            }
            v = src[addr];
        }
        xs[r][d] = v;
    }
    __syncthreads();
    {
        int r = tid >> 3, sub = tid & 7;
        float s = 0.f, s2 = 0.f;
        #pragma unroll
        for (int kk = 0; kk < 16; kk++) {
            float x = xs[r][sub + 8 * kk];
            s += x; s2 += x * x;
        }
        #pragma unroll
        for (int o = 4; o; o >>= 1) {
            s  += __shfl_xor_sync(0xffffffffu, s,  o);
            s2 += __shfl_xor_sync(0xffffffffu, s2, o);
        }
        float mean = s * (1.f / 128.f);
        float var  = s2 * (1.f / 128.f) - mean * mean;
        float rs   = rsqrtf(var + 1e-5f);
        #pragma unroll
        for (int kk = 0; kk < 16; kk++) {
            int d = sub + 8 * kk;
            xs[r][d] = (xs[r][d] - mean) * rs * lnw[d] + lnb[d];
        }
    }
    __syncthreads();

    const int j  = tid & 127;
    const int rb = tid >> 7;
    float acc[16];
    float bj = bias[j];
    #pragma unroll
    for (int i = 0; i < 16; i++) acc[i] = bj;
    for (int d = 0; d < 128; d++) {
        float wv = Wm[d * 128 + j];
        #pragma unroll
        for (int i = 0; i < 16; i++)
            acc[i] = fmaf(xs[rb * 16 + i][d], wv, acc[i]);
    }
    #pragma unroll
    for (int i = 0; i < 16; i++) {
        int row = row0 + rb * 16 + i;
        if (row < nrows) out[row * 128 + j] = f_tf32(acc[i]);
    }
}

// =====================================================================
// Kernel 2: tensor-core flash-style attention (tf32 mma.sync), key-split.
// 8 warps = 4 heads x 2 m-halves. Q frags in registers. K/V share one buffer.
// =====================================================================
#define SMEM_FLOATS (64*VSTRIDE + 4*32*PSTRIDE + 2*32*PSTRIDE)

__global__ __launch_bounds__(256, 2)
void attn3_kernel(const float* __restrict__ Wl, const int* __restrict__ vis)
{
    extern __shared__ float sm[];
    float* KV = sm;                          // K: [64][132], V: [64][136]
    float* Ps = KV + 64 * VSTRIDE;           // [4][32][68] (warp-private regions)
    float* As = Ps + 4 * 32 * PSTRIDE;       // [32][68]
    float* Bs = As + 32 * PSTRIDE;           // [32][68]

    const int tid  = threadIdx.x;
    const int lane = tid & 31, w = tid >> 5;
    const int h    = w & 3;                  // head
    const int half = w >> 2;                 // m-half (16 q rows)
    const int gid  = lane >> 2;              // 0..7
    const int tig  = lane & 3;               // 0..3

    const int sp = blockIdx.x / QT;
    const int qt = blockIdx.x % QT;
    const int q0 = qt * BQ;
    const int t0 = (NT_TOT * sp) / SPLITS;
    const int t1 = (NT_TOT * (sp + 1)) / SPLITS;

    // ---- Q A-fragments: registers for the whole kernel ----
    unsigned aQ[4][4];
    {
        const float* qp = g_qh + (q0 + half * 16 + gid) * 128 + h * 32 + tig;
        #pragma unroll
        for (int ks = 0; ks < 4; ks++) {
            aQ[ks][0] = __float_as_uint(__ldg(qp + ks * 8));
            aQ[ks][1] = __float_as_uint(__ldg(qp + 8 * 128 + ks * 8));
            aQ[ks][2] = __float_as_uint(__ldg(qp + ks * 8 + 4));
            aQ[ks][3] = __float_as_uint(__ldg(qp + 8 * 128 + ks * 8 + 4));
        }
    }

    float o[4][4];
    #pragma unroll
    for (int nt = 0; nt < 4; nt++)
        #pragma unroll
        for (int e = 0; e < 4; e++) o[nt][e] = 0.f;
    float ssum0 = 0.f, ssum1 = 0.f;

    for (int t = t0; t < t1; t++) {
        const int jb = t * TKK;
        __syncthreads();                     // prev phase B done: KV + A/B free

        // ---- stage K tile [64][132] ----
        #pragma unroll
        for (int i = 0; i < 8; i++) {
            int idx4 = tid + 256 * i;
            int j = idx4 >> 5, d4 = idx4 & 31;
            float4 v = ((const float4*)g_kh)[(jb + j) * 32 + d4];
            ((float4*)(KV + j * KSTRIDE))[d4] = v;
        }
        // ---- stage fused (A,B) coefs ----
        #pragma unroll
        for (int i = 0; i < 2; i++) {
            int idx4 = tid + 256 * i;        // 512 float4 = 32q x 16 chunks
            int q = idx4 >> 4, c4 = idx4 & 15;
            int qrow = q0 + q;
            int jg = jb + c4 * 4;
            float Aa[4], Bb[4];
            if (qrow < QN && jg + 3 < NKK) {
                const float4 wv = *(const float4*)(Wl + (size_t)qrow * NKK + jg);
                const int4   vv = *(const int4*) (vis + (size_t)qrow * NKK + jg);
                Aa[0] = vv.x ? SCALE * wv.x : 0.f;  Bb[0] = vv.x ? 0.f : -NEGBIG * wv.x;
                Aa[1] = vv.y ? SCALE * wv.y : 0.f;  Bb[1] = vv.y ? 0.f : -NEGBIG * wv.y;
                Aa[2] = vv.z ? SCALE * wv.z : 0.f;  Bb[2] = vv.z ? 0.f : -NEGBIG * wv.z;
                Aa[3] = vv.w ? SCALE * wv.w : 0.f;  Bb[3] = vv.w ? 0.f : -NEGBIG * wv.w;
            } else {
                #pragma unroll
                for (int e = 0; e < 4; e++) {
                    int jge = jg + e;
                    float av = 0.f, bv = -NEGBIG;
                    if (qrow < QN && jge < NKK) {
                        float wv = Wl[(size_t)qrow * NKK + jge];
                        int   vb = vis[(size_t)qrow * NKK + jge];
                        if (vb) { av = SCALE * wv; bv = 0.f; }
                        else    { av = 0.f;        bv = -NEGBIG * wv; }
                    }
                    Aa[e] = av; Bb[e] = bv;
                }
            }
            *(float4*)(As + q * PSTRIDE + c4 * 4) = make_float4(Aa[0], Aa[1], Aa[2], Aa[3]);
            *(float4*)(Bs + q * PSTRIDE + c4 * 4) = make_float4(Bb[0], Bb[1], Bb[2], Bb[3]);
        }
        __syncthreads();

        // ---- phase A: S[32x64] per head (8 n-tiles, 4 k-steps) ----
        float c[8][4];
        #pragma unroll
        for (int nt = 0; nt < 8; nt++)
            #pragma unroll
            for (int e = 0; e < 4; e++) c[nt][e] = 0.f;

        #pragma unroll
        for (int ks = 0; ks < 4; ks++) {
            #pragma unroll
            for (int nt = 0; nt < 8; nt++) {
                const float* kp = KV + (nt * 8 + gid) * KSTRIDE + h * 32 + ks * 8 + tig;
                unsigned b0 = __float_as_uint(kp[0]);
                unsigned b1 = __float_as_uint(kp[4]);
                mma_tf32(c[nt], aQ[ks], b0, b1);
            }
        }

        // ---- exp + tf32-round + store P (warp-private Ps region) ----
        {
            const int qlo = half * 16 + gid;
            #pragma unroll
            for (int nt = 0; nt < 8; nt++) {
                const int kc = nt * 8 + 2 * tig;
                float2 Alo = *(const float2*)(As + qlo * PSTRIDE + kc);
                float2 Blo = *(const float2*)(Bs + qlo * PSTRIDE + kc);
                float2 Ahi = *(const float2*)(As + (qlo + 8) * PSTRIDE + kc);
                float2 Bhi = *(const float2*)(Bs + (qlo + 8) * PSTRIDE + kc);
                float p0 = f_tf32(__expf(fmaf(Alo.x, c[nt][0], Blo.x)));
                float p1 = f_tf32(__expf(fmaf(Alo.y, c[nt][1], Blo.y)));
                float p2 = f_tf32(__expf(fmaf(Ahi.x, c[nt][2], Bhi.x)));
                float p3 = f_tf32(__expf(fmaf(Ahi.y, c[nt][3], Bhi.y)));
                ssum0 += p0 + p1;
                ssum1 += p2 + p3;
                *(float2*)(Ps + (h * 32 + qlo) * PSTRIDE + kc)     = make_float2(p0, p1);
                *(float2*)(Ps + (h * 32 + qlo + 8) * PSTRIDE + kc) = make_float2(p2, p3);
            }
        }
        __syncthreads();                     // all warps done reading K

        // ---- stage V tile [64][136] into the same buffer ----
        #pragma unroll
        for (int i = 0; i < 8; i++) {
            int idx4 = tid + 256 * i;
            int j = idx4 >> 5, d4 = idx4 & 31;
            float4 v = ((const float4*)g_vh)[(jb + j) * 32 + d4];
            ((float4*)(KV + j * VSTRIDE))[d4] = v;
        }
        __syncthreads();                     // V staged (also orders Ps within warp)

        // ---- phase B: O[32x32] per head += P[32x64] @ V[64x32] ----
        unsigned pa[8][4];
        {
            const float* pp = Ps + (h * 32 + half * 16 + gid) * PSTRIDE + tig;
            #pragma unroll
            for (int ks = 0; ks < 8; ks++) {
                pa[ks][0] = __float_as_uint(pp[ks * 8]);
                pa[ks][1] = __float_as_uint(pp[8 * PSTRIDE + ks * 8]);
                pa[ks][2] = __float_as_uint(pp[ks * 8 + 4]);
                pa[ks][3] = __float_as_uint(pp[8 * PSTRIDE + ks * 8 + 4]);
            }
        }
        #pragma unroll
        for (int ks = 0; ks < 8; ks++) {
            #pragma unroll
            for (int nt = 0; nt < 4; nt++) {
                const float* vp = KV + (ks * 8 + tig) * VSTRIDE + h * 32 + nt * 8 + gid;
                unsigned b0 = __float_as_uint(vp[0]);
                unsigned b1 = __float_as_uint(vp[4 * VSTRIDE]);
                mma_tf32(o[nt], pa[ks], b0, b1);
            }
        }
    }

    // ---- ssum: reduce over tig (4 lanes of quad) ----
    ssum0 += __shfl_xor_sync(0xffffffffu, ssum0, 1);
    ssum0 += __shfl_xor_sync(0xffffffffu, ssum0, 2);
    ssum1 += __shfl_xor_sync(0xffffffffu, ssum1, 1);
    ssum1 += __shfl_xor_sync(0xffffffffu, ssum1, 2);
    const int qr = q0 + half * 16 + gid;
    if (tig == 0) {
        g_ps[((size_t)sp * QPAD + qr) * 4 + h]     = ssum0;
        g_ps[((size_t)sp * QPAD + qr + 8) * 4 + h] = ssum1;
    }
    #pragma unroll
    for (int nt = 0; nt < 4; nt++) {
        const int col = h * 32 + nt * 8 + 2 * tig;
        *(float2*)(g_po + ((size_t)sp * QPAD + qr) * 128 + col)     = make_float2(o[nt][0], o[nt][1]);
        *(float2*)(g_po + ((size_t)sp * QPAD + qr + 8) * 128 + col) = make_float2(o[nt][2], o[nt][3]);
    }
}

// =====================================================================
// Kernel 3: combine partials + proj + skip + LN + MLP(GELU) + LN.
// =====================================================================
__device__ __forceinline__ void block_reduce2(float& s, float& s2, float* buf)
{
    #pragma unroll
    for (int o = 16; o; o >>= 1) {
        s  += __shfl_xor_sync(0xffffffffu, s,  o);
        s2 += __shfl_xor_sync(0xffffffffu, s2, o);
    }
    int w = threadIdx.x >> 5, l = threadIdx.x & 31;
    if (l == 0) { buf[w] = s; buf[4 + w] = s2; }
    __syncthreads();
    s  = buf[0] + buf[1] + buf[2] + buf[3];
    s2 = buf[4] + buf[5] + buf[6] + buf[7];
    __syncthreads();
}

__global__ __launch_bounds__(128)
void epilogue_kernel(const float* __restrict__ wp,   const float* __restrict__ bp,
                     const float* __restrict__ skip,
                     const float* __restrict__ prew, const float* __restrict__ preb,
                     const float* __restrict__ w1,   const float* __restrict__ b1,
                     const float* __restrict__ w2,   const float* __restrict__ b2,
                     const float* __restrict__ postw,const float* __restrict__ postb,
                     float* __restrict__ out)
{
    __shared__ float a[128];
    __shared__ float zsm[128];
    __shared__ float h[256];
    __shared__ float rbuf[8];

    const int row = blockIdx.x;
    const int j   = threadIdx.x;
    const int hd  = j >> 5;

    float denom = 0.f, av = 0.f;
    #pragma unroll
    for (int s = 0; s < SPLITS; s++) {
        size_t base = (size_t)s * QPAD + row;
        denom += g_ps[base * 4 + hd];
        av    += g_po[base * 128 + j];
    }
    a[j] = av / denom;
    __syncthreads();

    float t = bp[j];
    #pragma unroll 4
    for (int d = 0; d < 128; d++) t = fmaf(a[d], wp[d * 128 + j], t);
    t += skip[j * QN + row];

    float s = t, s2 = t * t;
    block_reduce2(s, s2, rbuf);
    float mean = s * (1.f / 128.f);
    float var  = s2 * (1.f / 128.f) - mean * mean;
    float zj = (t - mean) * rsqrtf(var + 1e-5f) * prew[j] + preb[j];
    zsm[j] = zj;
    __syncthreads();

    #pragma unroll
    for (int cc = 0; cc < 2; cc++) {
        int c = j + cc * 128;
        float hv = b1[c];
        #pragma unroll 4
        for (int d = 0; d < 128; d++) hv = fmaf(zsm[d], w1[d * 256 + c], hv);
        h[c] = 0.5f * hv * (1.0f + erff(hv * 0.70710678118654752f));
    }
    __syncthreads();

    float y = b2[j];
    #pragma unroll 4
    for (int c = 0; c < 256; c++) y = fmaf(h[c], w2[c * 128 + j], y);
    y += zj;

    float ps = y, ps2 = y * y;
    block_reduce2(ps, ps2, rbuf);
    float m2 = ps * (1.f / 128.f);
    float v2 = ps2 * (1.f / 128.f) - m2 * m2;
    out[j * QN + row] = (y - m2) * rsqrtf(v2 + 1e-5f) * postw[j] + postb[j];
}

// =====================================================================
extern "C" void kernel_launch(void* const* d_in, const int* in_sizes, int n_in,
                              void* d_out, int out_size)
{
    const float* q      = (const float*)d_in[0];
    const float* k      = (const float*)d_in[1];
    const float* v      = (const float*)d_in[2];
    const float* Wl     = (const float*)d_in[3];
    const int*   vis    = (const int*)  d_in[4];
    const float* skip   = (const float*)d_in[5];
    const float* qn_w   = (const float*)d_in[6];
    const float* qn_b   = (const float*)d_in[7];
    const float* kn_w   = (const float*)d_in[8];
    const float* kn_b   = (const float*)d_in[9];
    const float* vn_w   = (const float*)d_in[10];
    const float* vn_b   = (const float*)d_in[11];
    const float* pre_w  = (const float*)d_in[12];
    const float* pre_b  = (const float*)d_in[13];
    const float* post_w = (const float*)d_in[14];
    const float* post_b = (const float*)d_in[15];
    const float* wq     = (const float*)d_in[16];
    const float* bq     = (const float*)d_in[17];
    const float* wk     = (const float*)d_in[18];
    const float* bk     = (const float*)d_in[19];
    const float* wv     = (const float*)d_in[20];
    const float* bv     = (const float*)d_in[21];
    const float* wp     = (const float*)d_in[22];
    const float* bp     = (const float*)d_in[23];
    const float* w1     = (const float*)d_in[24];
    const float* b1     = (const float*)d_in[25];
    const float* w2     = (const float*)d_in[26];
    const float* b2     = (const float*)d_in[27];
    float* out = (float*)d_out;

    float *qh, *kh, *vh;
    cudaGetSymbolAddress((void**)&qh, g_qh);
    cudaGetSymbolAddress((void**)&kh, g_kh);
    cudaGetSymbolAddress((void**)&vh, g_vh);

    cudaFuncSetAttribute(attn3_kernel,
                         cudaFuncAttributeMaxDynamicSharedMemorySize,
                         SMEM_FLOATS * 4);

    ln_proj_kernel<<<(QN + 31) / 32, 256>>>(q, qn_w, qn_b, wq, bq, qh, QN, 0);
    ln_proj_kernel<<<NKK / 32, 256>>>(k, kn_w, kn_b, wk, bk, kh, NKK, 1);
    ln_proj_kernel<<<NKK / 32, 256>>>(v, vn_w, vn_b, wv, bv, vh, NKK, 1);

    attn3_kernel<<<SPLITS * QT, 256, SMEM_FLOATS * 4>>>(Wl, vis);

    epilogue_kernel<<<QN, 128>>>(wp, bp, skip, pre_w, pre_b,
                                 w1, b1, w2, b2, post_w, post_b, out);
}

// round 16
// speedup vs baseline: 17.7540x; 1.5585x over previous
#include <cuda_runtime.h>
#include <cuda_bf16.h>

// ---------------- problem constants ----------------
#define QN    2500
#define NKK   10080
#define NKP   10112      // 158*64
#define HWIMG 1680
#define SCALE 0.17677669529663687f
#define NEGBIG 3.402823466e38f

#define BQ     64
#define TKK    64
#define NT_TOT 158
#define SPLITS 11
#define QT     40        // ceil(2500/64)
#define QPAD   (QT*BQ)   // 2560
#define THREADS 512

// smem word offsets (32-bit words). K rows 68w, Vt rows 36w, W/vis rows 68w, Ps rows 36w.
#define KBUF   (64*68)           // 4352
#define VBUF   (128*36)          // 4608
#define WBUF   (64*68)           // 4352
#define KOFF   0
#define VOFF   (2*KBUF)          // 8704
#define WOFF   (VOFF + 2*VBUF)   // 17920
#define VIOFF  (WOFF + 2*WBUF)   // 26624
#define PSOFF  (VIOFF + 2*WBUF)  // 35328
#define SMEMW  (PSOFF + 4*64*36) // 44544 words = 178176 B

// ---------------- scratch ----------------
__device__ __nv_bfloat16 g_qh [QPAD * 128];
__device__ __nv_bfloat16 g_kh [NKP  * 128];
__device__ __nv_bfloat16 g_vt [128  * NKP];     // transposed: [d][key]
__device__ float g_po [SPLITS * QPAD * 128];
__device__ float g_ps [SPLITS * QPAD * 4];

// ---------------- helpers ----------------
__device__ __forceinline__ void mma_bf16(float c[4], const unsigned a[4],
                                         unsigned b0, unsigned b1)
{
    asm volatile(
        "mma.sync.aligned.m16n8k16.row.col.f32.bf16.bf16.f32 "
        "{%0,%1,%2,%3}, {%4,%5,%6,%7}, {%8,%9}, {%0,%1,%2,%3};\n"
        : "+f"(c[0]), "+f"(c[1]), "+f"(c[2]), "+f"(c[3])
        : "r"(a[0]), "r"(a[1]), "r"(a[2]), "r"(a[3]), "r"(b0), "r"(b1));
}
__device__ __forceinline__ void cpa16(unsigned dst, const void* src, int nbytes)
{
    asm volatile("cp.async.cg.shared.global [%0], [%1], 16, %2;\n"
                 :: "r"(dst), "l"(src), "r"(nbytes));
}
#define CP_COMMIT() asm volatile("cp.async.commit_group;\n" ::: "memory")
#define CP_WAIT1()  asm volatile("cp.async.wait_group 1;\n" ::: "memory")

// =====================================================================
// Kernel 1: LayerNorm + 128x128 projection -> bf16 outputs.
//   mode 0: q src [D,2500], out row-major, scaled by SCALE
//   mode 1: k src [N,D,28,60], out row-major
//   mode 2: v src [N,D,28,60], out TRANSPOSED [d][NKP]
// =====================================================================
__global__ __launch_bounds__(256)
void ln_proj_kernel(const float* __restrict__ src,
                    const float* __restrict__ lnw, const float* __restrict__ lnb,
                    const float* __restrict__ Wm,  const float* __restrict__ bias,
                    __nv_bfloat16* __restrict__ out, int nrows, int mode)
{
    __shared__ float xs[32][129];
    const int tid  = threadIdx.x;
    const int row0 = blockIdx.x * 32;

    #pragma unroll
    for (int i = 0; i < 16; i++) {
        int idx = tid + 256 * i;
        int r = idx & 31, d = idx >> 5;
        int row = row0 + r;
        float v = 0.f;
        if (row < nrows) {
            int addr;
            if (mode == 0) addr = d * QN + row;
            else {
                int n  = row / HWIMG;
                int hw = row - n * HWIMG;
                addr = (n * 128 + d) * HWIMG + hw;
            }
            v = src[addr];
        }
        xs[r][d] = v;
    }
    __syncthreads();
    {
        int r = tid >> 3, sub = tid & 7;
        float s = 0.f, s2 = 0.f;
        #pragma unroll
        for (int kk = 0; kk < 16; kk++) {
            float x = xs[r][sub + 8 * kk];
            s += x; s2 += x * x;
        }
        #pragma unroll
        for (int o = 4; o; o >>= 1) {
            s  += __shfl_xor_sync(0xffffffffu, s,  o);
            s2 += __shfl_xor_sync(0xffffffffu, s2, o);
        }
        float mean = s * (1.f / 128.f);
        float var  = s2 * (1.f / 128.f) - mean * mean;
        float rs   = rsqrtf(var + 1e-5f);
        #pragma unroll
        for (int kk = 0; kk < 16; kk++) {
            int d = sub + 8 * kk;
            xs[r][d] = (xs[r][d] - mean) * rs * lnw[d] + lnb[d];
        }
    }
    __syncthreads();

    const int j  = tid & 127;
    const int rb = tid >> 7;
    float acc[16];
    float bj = bias[j];
    #pragma unroll
    for (int i = 0; i < 16; i++) acc[i] = bj;
    for (int d = 0; d < 128; d++) {
        float wv = Wm[d * 128 + j];
        #pragma unroll
        for (int i = 0; i < 16; i++)
            acc[i] = fmaf(xs[rb * 16 + i][d], wv, acc[i]);
    }
    const float mul = (mode == 0) ? SCALE : 1.f;
    #pragma unroll
    for (int i = 0; i < 16; i++) {
        int row = row0 + rb * 16 + i;
        if (row < nrows) {
            __nv_bfloat16 bv = __float2bfloat16(acc[i] * mul);
            if (mode == 2) out[(size_t)j * NKP + row] = bv;
            else           out[row * 128 + j] = bv;
        }
    }
}

// =====================================================================
// Kernel 2: bf16 tensor-core attention, cp.async double-buffered pipeline.
// 16 warps = 4 heads x 4 m-chunks of 16 q-rows. 2 barriers/tile.
// =====================================================================
__global__ __launch_bounds__(THREADS, 1)
void attn4_kernel(const float* __restrict__ Wl, const int* __restrict__ vis)
{
    extern __shared__ float sm[];
    const unsigned smem_b = (unsigned)__cvta_generic_to_shared(sm);

    const int tid  = threadIdx.x;
    const int lane = tid & 31, w = tid >> 5;
    const int h    = w & 3;                  // head
    const int mq   = w >> 2;                 // m-chunk (16 rows)
    const int g    = lane >> 2;              // 0..7
    const int tig  = lane & 3;               // 0..3

    const int sp = blockIdx.x / QT;
    const int qt = blockIdx.x % QT;
    const int q0 = qt * BQ;
    const int t0 = (NT_TOT * sp) / SPLITS;
    const int t1 = (NT_TOT * (sp + 1)) / SPLITS;

    // ---- Q A-fragments in registers (pre-scaled by SCALE in ln_proj) ----
    unsigned aQ[2][4];
    {
        const unsigned* qpu = (const unsigned*)g_qh
                            + (q0 + mq * 16 + g) * 64 + h * 16 + tig;
        #pragma unroll
        for (int ks = 0; ks < 2; ks++) {
            aQ[ks][0] = qpu[ks * 8];
            aQ[ks][1] = qpu[512 + ks * 8];
            aQ[ks][2] = qpu[ks * 8 + 4];
            aQ[ks][3] = qpu[512 + ks * 8 + 4];
        }
    }

    float o[4][4];
    #pragma unroll
    for (int nt = 0; nt < 4; nt++)
        #pragma unroll
        for (int e = 0; e < 4; e++) o[nt][e] = 0.f;
    float ssum0 = 0.f, ssum1 = 0.f;

    // ---- stage one tile into buffer b ----
    auto stage_tile = [&](int t, int b) {
        const int jb = t * TKK;
        // K: 64 rows x 256B (row stride 272B)
        #pragma unroll
        for (int i = 0; i < 2; i++) {
            int c = tid + THREADS * i;
            int row = c >> 4, cw = c & 15;
            unsigned dst = smem_b + (KOFF + b * KBUF) * 4 + row * 272 + cw * 16;
            const char* src = (const char*)g_kh + ((size_t)(jb + row) * 128 + cw * 8) * 2;
            cpa16(dst, src, 16);
        }
        // Vt: 128 rows x 128B (row stride 144B)
        #pragma unroll
        for (int i = 0; i < 2; i++) {
            int c = tid + THREADS * i;
            int d = c >> 3, jw = c & 7;
            unsigned dst = smem_b + (VOFF + b * VBUF) * 4 + d * 144 + jw * 16;
            const char* src = (const char*)g_vt + ((size_t)d * NKP + jb + jw * 8) * 2;
            cpa16(dst, src, 16);
        }
        // W / vis: 64 rows x 256B (row stride 272B), zero-filled OOB
        #pragma unroll
        for (int i = 0; i < 2; i++) {
            int c = tid + THREADS * i;
            int qr = c >> 4, cw = c & 15;
            int qrow = q0 + qr;
            int col0 = jb + cw * 4;
            int nb = 0;
            if (qrow < QN) {
                nb = (NKK - col0) * 4;
                nb = nb < 0 ? 0 : (nb > 16 ? 16 : nb);
            }
            size_t off = (size_t)qrow * NKK + col0;
            const float* sw = (nb > 0) ? (Wl + off) : Wl;
            const int*   sv = (nb > 0) ? (vis + off) : vis;
            cpa16(smem_b + (WOFF  + b * WBUF) * 4 + qr * 272 + cw * 16, sw, nb);
            cpa16(smem_b + (VIOFF + b * WBUF) * 4 + qr * 272 + cw * 16, sv, nb);
        }
    };

    // ---- prologue: prefetch first two tiles ----
    stage_tile(t0, 0);
    CP_COMMIT();
    if (t0 + 1 < t1) stage_tile(t0 + 1, 1);
    CP_COMMIT();

    unsigned* Psu = (unsigned*)(sm + PSOFF);
    const int r0 = mq * 16 + g;

    for (int t = t0; t < t1; t++) {
        const int b  = (t - t0) & 1;
        const int jb = t * TKK;
        CP_WAIT1();
        __syncthreads();                     // buffer b ready, all warps aligned

        const unsigned* Ku = (const unsigned*)(sm + KOFF + b * KBUF);
        const unsigned* Vu = (const unsigned*)(sm + VOFF + b * VBUF);
        const float*    Wb = sm + WOFF + b * WBUF;
        const int*      Vb = (const int*)(sm + VIOFF + b * WBUF);

        // ---- phase A: S[16 x 64] per warp ----
        float c[8][4];
        #pragma unroll
        for (int nt = 0; nt < 8; nt++)
            #pragma unroll
            for (int e = 0; e < 4; e++) c[nt][e] = 0.f;

        #pragma unroll
        for (int ks = 0; ks < 2; ks++) {
            #pragma unroll
            for (int nt = 0; nt < 8; nt++) {
                const unsigned* kp = Ku + (nt * 8 + g) * 68 + h * 16 + ks * 8 + tig;
                mma_bf16(c[nt], aQ[ks], kp[0], kp[4]);
            }
        }

        // ---- exp + mask fold + bf16 pack + P store ----
        {
            const int limit = NKK - jb;
            const int r0w = r0 * 68, r1w = r0w + 8 * 68;
            #pragma unroll
            for (int nt = 0; nt < 8; nt++) {
                const int kc = nt * 8 + 2 * tig;
                float2 w0 = *(const float2*)(Wb + r0w + kc);
                float2 w1 = *(const float2*)(Wb + r1w + kc);
                int2   v0 = *(const int2*)(Vb + r0w + kc);
                int2   v1 = *(const int2*)(Vb + r1w + kc);
                float p00 = __expf(w0.x * (v0.x ? c[nt][0] : -NEGBIG));
                float p01 = __expf(w0.y * (v0.y ? c[nt][1] : -NEGBIG));
                float p10 = __expf(w1.x * (v1.x ? c[nt][2] : -NEGBIG));
                float p11 = __expf(w1.y * (v1.y ? c[nt][3] : -NEGBIG));
                if (kc     >= limit) { p00 = 0.f; p10 = 0.f; }
                if (kc + 1 >= limit) { p01 = 0.f; p11 = 0.f; }
                ssum0 += p00 + p01;
                ssum1 += p10 + p11;
                unsigned P0, P1;
                asm("cvt.rn.bf16x2.f32 %0, %1, %2;" : "=r"(P0) : "f"(p01), "f"(p00));
                asm("cvt.rn.bf16x2.f32 %0, %1, %2;" : "=r"(P1) : "f"(p11), "f"(p10));
                Psu[(h * 64 + r0) * 36 + nt * 4 + tig]     = P0;
                Psu[(h * 64 + r0 + 8) * 36 + nt * 4 + tig] = P1;
            }
        }
        __syncwarp();                        // P is warp-private

        // ---- phase B: O[16 x 32] per warp += P[16x64] @ V[64x32] ----
        unsigned pa[4][4];
        {
            const unsigned* pp0 = Psu + (h * 64 + r0) * 36 + tig;
            #pragma unroll
            for (int ks = 0; ks < 4; ks++) {
                pa[ks][0] = pp0[ks * 8];
                pa[ks][1] = pp0[288 + ks * 8];
                pa[ks][2] = pp0[ks * 8 + 4];
                pa[ks][3] = pp0[288 + ks * 8 + 4];
            }
        }
        #pragma unroll
        for (int ks = 0; ks < 4; ks++) {
            #pragma unroll
            for (int nt = 0; nt < 4; nt++) {
                const unsigned* vp = Vu + (h * 32 + nt * 8 + g) * 36 + ks * 8 + tig;
                mma_bf16(o[nt], pa[ks], vp[0], vp[4]);
            }
        }
        __syncthreads();                     // all warps done with buffer b

        if (t + 2 < t1) stage_tile(t + 2, b);
        CP_COMMIT();                         // (possibly empty group)
    }

    // ---- reduce ssum over quad, write partials ----
    ssum0 += __shfl_xor_sync(0xffffffffu, ssum0, 1);
    ssum0 += __shfl_xor_sync(0xffffffffu, ssum0, 2);
    ssum1 += __shfl_xor_sync(0xffffffffu, ssum1, 1);
    ssum1 += __shfl_xor_sync(0xffffffffu, ssum1, 2);
    const int qr = q0 + r0;
    if (tig == 0) {
        g_ps[((size_t)sp * QPAD + qr) * 4 + h]     = ssum0;
        g_ps[((size_t)sp * QPAD + qr + 8) * 4 + h] = ssum1;
    }
    #pragma unroll
    for (int nt = 0; nt < 4; nt++) {
        const int col = h * 32 + nt * 8 + 2 * tig;
        *(float2*)(g_po + ((size_t)sp * QPAD + qr) * 128 + col)     = make_float2(o[nt][0], o[nt][1]);
        *(float2*)(g_po + ((size_t)sp * QPAD + qr + 8) * 128 + col) = make_float2(o[nt][2], o[nt][3]);
    }
}

// =====================================================================
// Kernel 3: combine partials + proj + skip + LN + MLP(GELU) + LN.
// =====================================================================
__device__ __forceinline__ void block_reduce2(float& s, float& s2, float* buf)
{
    #pragma unroll
    for (int o = 16; o; o >>= 1) {
        s  += __shfl_xor_sync(0xffffffffu, s,  o);
        s2 += __shfl_xor_sync(0xffffffffu, s2, o);
    }
    int w = threadIdx.x >> 5, l = threadIdx.x & 31;
    if (l == 0) { buf[w] = s; buf[4 + w] = s2; }
    __syncthreads();
    s  = buf[0] + buf[1] + buf[2] + buf[3];
    s2 = buf[4] + buf[5] + buf[6] + buf[7];
    __syncthreads();
}

__global__ __launch_bounds__(128)
void epilogue_kernel(const float* __restrict__ wp,   const float* __restrict__ bp,
                     const float* __restrict__ skip,
                     const float* __restrict__ prew, const float* __restrict__ preb,
                     const float* __restrict__ w1,   const float* __restrict__ b1,
                     const float* __restrict__ w2,   const float* __restrict__ b2,
                     const float* __restrict__ postw,const float* __restrict__ postb,
                     float* __restrict__ out)
{
    __shared__ float a[128];
    __shared__ float zsm[128];
    __shared__ float h[256];
    __shared__ float rbuf[8];

    const int row = blockIdx.x;
    const int j   = threadIdx.x;
    const int hd  = j >> 5;

    float denom = 0.f, av = 0.f;
    #pragma unroll
    for (int s = 0; s < SPLITS; s++) {
        size_t base = (size_t)s * QPAD + row;
        denom += g_ps[base * 4 + hd];
        av    += g_po[base * 128 + j];
    }
    a[j] = av / denom;
    __syncthreads();

    // out-projection (4-way accumulator ILP)
    float t0 = 0.f, t1 = 0.f, t2 = 0.f, t3 = 0.f;
    #pragma unroll 8
    for (int d = 0; d < 128; d += 4) {
        t0 = fmaf(a[d],     wp[d * 128 + j],       t0);
        t1 = fmaf(a[d + 1], wp[(d + 1) * 128 + j], t1);
        t2 = fmaf(a[d + 2], wp[(d + 2) * 128 + j], t2);
        t3 = fmaf(a[d + 3], wp[(d + 3) * 128 + j], t3);
    }
    float t = bp[j] + (t0 + t1) + (t2 + t3);
    t += skip[j * QN + row];

    float s = t, s2 = t * t;
    block_reduce2(s, s2, rbuf);
    float mean = s * (1.f / 128.f);
    float var  = s2 * (1.f / 128.f) - mean * mean;
    float zj = (t - mean) * rsqrtf(var + 1e-5f) * prew[j] + preb[j];
    zsm[j] = zj;
    __syncthreads();

    #pragma unroll
    for (int cc = 0; cc < 2; cc++) {
        int c = j + cc * 128;
        float h0 = 0.f, h1 = 0.f, h2 = 0.f, h3 = 0.f;
        #pragma unroll 8
        for (int d = 0; d < 128; d += 4) {
            h0 = fmaf(zsm[d],     w1[d * 256 + c],       h0);
            h1 = fmaf(zsm[d + 1], w1[(d + 1) * 256 + c], h1);
            h2 = fmaf(zsm[d + 2], w1[(d + 2) * 256 + c], h2);
            h3 = fmaf(zsm[d + 3], w1[(d + 3) * 256 + c], h3);
        }
        float hv = b1[c] + (h0 + h1) + (h2 + h3);
        h[c] = 0.5f * hv * (1.0f + erff(hv * 0.70710678118654752f));
    }
    __syncthreads();

    float y0 = 0.f, y1 = 0.f, y2 = 0.f, y3 = 0.f;
    #pragma unroll 8
    for (int c = 0; c < 256; c += 4) {
        y0 = fmaf(h[c],     w2[c * 128 + j],       y0);
        y1 = fmaf(h[c + 1], w2[(c + 1) * 128 + j], y1);
        y2 = fmaf(h[c + 2], w2[(c + 2) * 128 + j], y2);
        y3 = fmaf(h[c + 3], w2[(c + 3) * 128 + j], y3);
    }
    float y = b2[j] + (y0 + y1) + (y2 + y3) + zj;

    float ps = y, ps2 = y * y;
    block_reduce2(ps, ps2, rbuf);
    float m2 = ps * (1.f / 128.f);
    float v2 = ps2 * (1.f / 128.f) - m2 * m2;
    out[j * QN + row] = (y - m2) * rsqrtf(v2 + 1e-5f) * postw[j] + postb[j];
}

// =====================================================================
extern "C" void kernel_launch(void* const* d_in, const int* in_sizes, int n_in,
                              void* d_out, int out_size)
{
    const float* q      = (const float*)d_in[0];
    const float* k      = (const float*)d_in[1];
    const float* v      = (const float*)d_in[2];
    const float* Wl     = (const float*)d_in[3];
    const int*   vis    = (const int*)  d_in[4];
    const float* skip   = (const float*)d_in[5];
    const float* qn_w   = (const float*)d_in[6];
    const float* qn_b   = (const float*)d_in[7];
    const float* kn_w   = (const float*)d_in[8];
    const float* kn_b   = (const float*)d_in[9];
    const float* vn_w   = (const float*)d_in[10];
    const float* vn_b   = (const float*)d_in[11];
    const float* pre_w  = (const float*)d_in[12];
    const float* pre_b  = (const float*)d_in[13];
    const float* post_w = (const float*)d_in[14];
    const float* post_b = (const float*)d_in[15];
    const float* wq     = (const float*)d_in[16];
    const float* bq     = (const float*)d_in[17];
    const float* wk     = (const float*)d_in[18];
    const float* bk     = (const float*)d_in[19];
    const float* wv     = (const float*)d_in[20];
    const float* bv     = (const float*)d_in[21];
    const float* wp     = (const float*)d_in[22];
    const float* bp     = (const float*)d_in[23];
    const float* w1     = (const float*)d_in[24];
    const float* b1     = (const float*)d_in[25];
    const float* w2     = (const float*)d_in[26];
    const float* b2     = (const float*)d_in[27];
    float* out = (float*)d_out;

    __nv_bfloat16 *qh, *kh, *vt;
    cudaGetSymbolAddress((void**)&qh, g_qh);
    cudaGetSymbolAddress((void**)&kh, g_kh);
    cudaGetSymbolAddress((void**)&vt, g_vt);

    cudaFuncSetAttribute(attn4_kernel,
                         cudaFuncAttributeMaxDynamicSharedMemorySize,
                         SMEMW * 4);

    ln_proj_kernel<<<(QN + 31) / 32, 256>>>(q, qn_w, qn_b, wq, bq, qh, QN, 0);
    ln_proj_kernel<<<NKK / 32, 256>>>(k, kn_w, kn_b, wk, bk, kh, NKK, 1);
    ln_proj_kernel<<<NKK / 32, 256>>>(v, vn_w, vn_b, wv, bv, vt, NKK, 2);

    attn4_kernel<<<SPLITS * QT, THREADS, SMEMW * 4>>>(Wl, vis);

    epilogue_kernel<<<QN, 128>>>(wp, bp, skip, pre_w, pre_b,
                                 w1, b1, w2, b2, post_w, post_b, out);
}